// round 1
// baseline (speedup 1.0000x reference)
#include <cuda_runtime.h>
#include <stdint.h>

// out[b,n,j] = X[b,n,10j+9] / X[b,n,10j] - 2
// X: (64, 512, 4000) fp32 contiguous; out: (64, 512, 400) fp32.
// One thread per output element. Stores fully coalesced; loads strided
// (40 B apart across lanes) but every 32B sector of the input is needed
// by *some* lane, so DRAM traffic is the full input either way.

static constexpr int T_LEN   = 4000;
static constexpr int W_LEN   = 400;   // (4000-10)/10 + 1
static constexpr int N_ROWS  = 64 * 512;
static constexpr int N_OUT   = N_ROWS * W_LEN;   // 13,107,200

__global__ __launch_bounds__(256) void ts_return_kernel(
    const float* __restrict__ X, float* __restrict__ out)
{
    uint32_t idx = blockIdx.x * blockDim.x + threadIdx.x;
    if (idx >= (uint32_t)N_OUT) return;

    uint32_t row = idx / W_LEN;          // ptxas -> IMAD.WIDE trick
    uint32_t j   = idx - row * W_LEN;

    const float* rowp = X + (size_t)row * T_LEN + (uint32_t)(10u * j);
    float first = rowp[0];
    float last  = rowp[9];

    out[idx] = __fdividef(last, first) - 2.0f;
}

extern "C" void kernel_launch(void* const* d_in, const int* in_sizes, int n_in,
                              void* d_out, int out_size)
{
    const float* X = (const float*)d_in[0];
    float* out = (float*)d_out;
    int threads = 256;
    int blocks = (N_OUT + threads - 1) / threads;   // 51200
    ts_return_kernel<<<blocks, threads>>>(X, out);
}